// round 15
// baseline (speedup 1.0000x reference)
#include <cuda_runtime.h>
#include <cuda_fp16.h>
#include <math_constants.h>

// CollectNeighbourAverageAndMax: V=100000, K=32, F=64
// Round 15: champion structure; convert kernel at 4 floats/thread (max TLP)
// to shorten its latency-limited tail — following the measured trend that
// more convert threads -> less end-to-end time (R5 8/t beat R8 16/t).
// Kernel B untouched: 474 MB @ LTS chip cap (~14.7 TB/s), at the hardware
// floor across 5 consistent measurements.

#define V_MAX 100000
#define F_DIM 64

__device__ __half g_xh[(size_t)V_MAX * F_DIM];  // 12.8 MB fp16 scratch

// ---- Kernel A: convert x [V,64] f32 -> f16, 4 floats per thread -----------
__global__ void __launch_bounds__(256)
convert_x_kernel(const float* __restrict__ x, int n4) {
    const int i = blockIdx.x * blockDim.x + threadIdx.x;
    if (i >= n4) return;
    const float4 v = reinterpret_cast<const float4*>(x)[i];
    const __half2 h0 = __floats2half2_rn(v.x, v.y);
    const __half2 h1 = __floats2half2_rn(v.z, v.w);
    uint2 p;
    p.x = *reinterpret_cast<const unsigned*>(&h0);
    p.y = *reinterpret_cast<const unsigned*>(&h1);
    reinterpret_cast<uint2*>(g_xh)[i] = p;
}

// ---- Kernel B: warp-per-vertex, 4 neighbors per LDG.128 (UNCHANGED) -------
// quad = lane>>3 : which of the 4 concurrently-fetched neighbors lane serves
// sub  = lane&7  : 16-byte (8-feature) chunk of the 128 B row
__global__ void __launch_bounds__(256, 8)
collect_nbr_avg_max_q(const int* __restrict__ idxs,
                      float* __restrict__ out,
                      int V) {
    const int warp_id = (blockIdx.x * blockDim.x + threadIdx.x) >> 5;
    if (warp_id >= V) return;
    const int lane = threadIdx.x & 31;
    const int quad = lane >> 3;
    const int sub = lane & 7;
    const int q8 = lane & 24;  // quad * 8

    // This lane's index stream: 8 neighbors owned by its quad (one 128B line
    // per warp -> 1 LTS fetch, L1 hits after).
    const int* __restrict__ ip = idxs + (size_t)warp_id * 32 + q8;
    const char* base = reinterpret_cast<const char*>(g_xh) + (sub << 4);

    __half2 s0, s1, s2, s3;
    s0 = s1 = s2 = s3 = __float2half2_rn(0.0f);
    __half2 m0, m1, m2, m3;
    m0 = m1 = m2 = m3 = __float2half2_rn(-CUDART_INF_F);

#pragma unroll
    for (int k = 0; k < 8; ++k) {
        const int off = ip[k] << 7;  // row byte offset (rows are 128 B)
        const uint4 u = *reinterpret_cast<const uint4*>(base + off);
        const __half2 a0 = *reinterpret_cast<const __half2*>(&u.x);
        const __half2 a1 = *reinterpret_cast<const __half2*>(&u.y);
        const __half2 a2 = *reinterpret_cast<const __half2*>(&u.z);
        const __half2 a3 = *reinterpret_cast<const __half2*>(&u.w);
        s0 = __hadd2(s0, a0);
        s1 = __hadd2(s1, a1);
        s2 = __hadd2(s2, a2);
        s3 = __hadd2(s3, a3);
        m0 = __hmax2(m0, a0);
        m1 = __hmax2(m1, a1);
        m2 = __hmax2(m2, a2);
        m3 = __hmax2(m3, a3);
    }

    // Reduce across the 4 quads (lane bits 3,4): disjoint neighbor sets,
    // same feature chunk.
#pragma unroll
    for (int d = 8; d <= 16; d <<= 1) {
        unsigned t;
        t = __shfl_xor_sync(0xffffffffu, *reinterpret_cast<unsigned*>(&s0), d);
        s0 = __hadd2(s0, *reinterpret_cast<__half2*>(&t));
        t = __shfl_xor_sync(0xffffffffu, *reinterpret_cast<unsigned*>(&s1), d);
        s1 = __hadd2(s1, *reinterpret_cast<__half2*>(&t));
        t = __shfl_xor_sync(0xffffffffu, *reinterpret_cast<unsigned*>(&s2), d);
        s2 = __hadd2(s2, *reinterpret_cast<__half2*>(&t));
        t = __shfl_xor_sync(0xffffffffu, *reinterpret_cast<unsigned*>(&s3), d);
        s3 = __hadd2(s3, *reinterpret_cast<__half2*>(&t));
        t = __shfl_xor_sync(0xffffffffu, *reinterpret_cast<unsigned*>(&m0), d);
        m0 = __hmax2(m0, *reinterpret_cast<__half2*>(&t));
        t = __shfl_xor_sync(0xffffffffu, *reinterpret_cast<unsigned*>(&m1), d);
        m1 = __hmax2(m1, *reinterpret_cast<__half2*>(&t));
        t = __shfl_xor_sync(0xffffffffu, *reinterpret_cast<unsigned*>(&m2), d);
        m2 = __hmax2(m2, *reinterpret_cast<__half2*>(&t));
        t = __shfl_xor_sync(0xffffffffu, *reinterpret_cast<unsigned*>(&m3), d);
        m3 = __hmax2(m3, *reinterpret_cast<__half2*>(&t));
    }

    // Mean = sum * 2^-5 (exact in fp16).
    const __half2 inv32 = __float2half2_rn(0.03125f);
    s0 = __hmul2(s0, inv32);
    s1 = __hmul2(s1, inv32);
    s2 = __hmul2(s2, inv32);
    s3 = __hmul2(s3, inv32);

    // One STG.128 per lane:
    //  quad0: mean[8sub..+4)  quad1: mean[8sub+4..+8)
    //  quad2: max [8sub..+4)  quad3: max [8sub+4..+8)
    __half2 lo, hi;
    float* orow = out + (size_t)warp_id * 128;
    float* ptr;
    if (quad == 0)      { lo = s0; hi = s1; ptr = orow + 8 * sub; }
    else if (quad == 1) { lo = s2; hi = s3; ptr = orow + 8 * sub + 4; }
    else if (quad == 2) { lo = m0; hi = m1; ptr = orow + 64 + 8 * sub; }
    else                { lo = m2; hi = m3; ptr = orow + 64 + 8 * sub + 4; }

    const float2 fa = __half22float2(lo);
    const float2 fb = __half22float2(hi);
    *reinterpret_cast<float4*>(ptr) = make_float4(fa.x, fa.y, fb.x, fb.y);
}

extern "C" void kernel_launch(void* const* d_in, const int* in_sizes, int n_in,
                              void* d_out, int out_size) {
    const float* x = (const float*)d_in[0];   // [V, 64] f32
    const int* idxs = (const int*)d_in[1];    // [V, 32] i32
    float* out = (float*)d_out;               // [V, 128] f32

    const int V = in_sizes[1] / 32;

    const int n4 = V * (F_DIM / 4);
    convert_x_kernel<<<(n4 + 255) / 256, 256>>>(x, n4);

    const int threads = 256;  // 8 warps -> 8 vertices/block
    const int warps_per_block = threads / 32;
    const int blocks = (V + warps_per_block - 1) / warps_per_block;
    collect_nbr_avg_max_q<<<blocks, threads>>>(idxs, out, V);
}

// round 16
// speedup vs baseline: 1.0787x; 1.0787x over previous
#include <cuda_runtime.h>
#include <cuda_fp16.h>
#include <math_constants.h>

// CollectNeighbourAverageAndMax: V=100000, K=32, F=64
// Round 16: champion (R11) form + streaming-store hint on the output.
//  - convert: 8 floats/thread (measured sweet spot: 4/t and 16/t both worse)
//  - gather: at the LTS chip cap (474 MB @ ~14.7 TB/s) across 6 runs
//  - NEW: out[] written with st.global.cs (evict-first). out is write-once,
//    never re-read; keeping its 51 MB out of L2 protects the 12.8 MB g_xh
//    table from eviction (observed DRAM read traffic > compulsory).

#define V_MAX 100000
#define F_DIM 64

__device__ __half g_xh[(size_t)V_MAX * F_DIM];  // 12.8 MB fp16 scratch

__device__ __forceinline__ void stg_cs_f4(float* p, float a, float b,
                                          float c, float d) {
    asm volatile("st.global.cs.v4.f32 [%0], {%1, %2, %3, %4};"
                 :: "l"(p), "f"(a), "f"(b), "f"(c), "f"(d) : "memory");
}

// ---- Kernel A: convert x [V,64] f32 -> f16, 8 floats per thread -----------
__global__ void __launch_bounds__(256)
convert_x_kernel(const float* __restrict__ x, int n8) {
    const int i = blockIdx.x * blockDim.x + threadIdx.x;
    if (i >= n8) return;
    const float4 v0 = reinterpret_cast<const float4*>(x)[2 * i];
    const float4 v1 = reinterpret_cast<const float4*>(x)[2 * i + 1];
    const __half2 h0 = __floats2half2_rn(v0.x, v0.y);
    const __half2 h1 = __floats2half2_rn(v0.z, v0.w);
    const __half2 h2 = __floats2half2_rn(v1.x, v1.y);
    const __half2 h3 = __floats2half2_rn(v1.z, v1.w);
    uint4 p;
    p.x = *reinterpret_cast<const unsigned*>(&h0);
    p.y = *reinterpret_cast<const unsigned*>(&h1);
    p.z = *reinterpret_cast<const unsigned*>(&h2);
    p.w = *reinterpret_cast<const unsigned*>(&h3);
    reinterpret_cast<uint4*>(g_xh)[i] = p;
}

// ---- Kernel B: warp-per-vertex, 4 neighbors per LDG.128 -------------------
// quad = lane>>3 : which of the 4 concurrently-fetched neighbors lane serves
// sub  = lane&7  : 16-byte (8-feature) chunk of the 128 B row
__global__ void __launch_bounds__(256, 8)
collect_nbr_avg_max_q(const int* __restrict__ idxs,
                      float* __restrict__ out,
                      int V) {
    const int warp_id = (blockIdx.x * blockDim.x + threadIdx.x) >> 5;
    if (warp_id >= V) return;
    const int lane = threadIdx.x & 31;
    const int quad = lane >> 3;
    const int sub = lane & 7;
    const int q8 = lane & 24;  // quad * 8

    // This lane's index stream: 8 neighbors owned by its quad (one 128B line
    // per warp -> 1 LTS fetch, L1 hits after).
    const int* __restrict__ ip = idxs + (size_t)warp_id * 32 + q8;
    const char* base = reinterpret_cast<const char*>(g_xh) + (sub << 4);

    __half2 s0, s1, s2, s3;
    s0 = s1 = s2 = s3 = __float2half2_rn(0.0f);
    __half2 m0, m1, m2, m3;
    m0 = m1 = m2 = m3 = __float2half2_rn(-CUDART_INF_F);

#pragma unroll
    for (int k = 0; k < 8; ++k) {
        const int off = ip[k] << 7;  // row byte offset (rows are 128 B)
        const uint4 u = *reinterpret_cast<const uint4*>(base + off);
        const __half2 a0 = *reinterpret_cast<const __half2*>(&u.x);
        const __half2 a1 = *reinterpret_cast<const __half2*>(&u.y);
        const __half2 a2 = *reinterpret_cast<const __half2*>(&u.z);
        const __half2 a3 = *reinterpret_cast<const __half2*>(&u.w);
        s0 = __hadd2(s0, a0);
        s1 = __hadd2(s1, a1);
        s2 = __hadd2(s2, a2);
        s3 = __hadd2(s3, a3);
        m0 = __hmax2(m0, a0);
        m1 = __hmax2(m1, a1);
        m2 = __hmax2(m2, a2);
        m3 = __hmax2(m3, a3);
    }

    // Reduce across the 4 quads (lane bits 3,4): disjoint neighbor sets,
    // same feature chunk.
#pragma unroll
    for (int d = 8; d <= 16; d <<= 1) {
        unsigned t;
        t = __shfl_xor_sync(0xffffffffu, *reinterpret_cast<unsigned*>(&s0), d);
        s0 = __hadd2(s0, *reinterpret_cast<__half2*>(&t));
        t = __shfl_xor_sync(0xffffffffu, *reinterpret_cast<unsigned*>(&s1), d);
        s1 = __hadd2(s1, *reinterpret_cast<__half2*>(&t));
        t = __shfl_xor_sync(0xffffffffu, *reinterpret_cast<unsigned*>(&s2), d);
        s2 = __hadd2(s2, *reinterpret_cast<__half2*>(&t));
        t = __shfl_xor_sync(0xffffffffu, *reinterpret_cast<unsigned*>(&s3), d);
        s3 = __hadd2(s3, *reinterpret_cast<__half2*>(&t));
        t = __shfl_xor_sync(0xffffffffu, *reinterpret_cast<unsigned*>(&m0), d);
        m0 = __hmax2(m0, *reinterpret_cast<__half2*>(&t));
        t = __shfl_xor_sync(0xffffffffu, *reinterpret_cast<unsigned*>(&m1), d);
        m1 = __hmax2(m1, *reinterpret_cast<__half2*>(&t));
        t = __shfl_xor_sync(0xffffffffu, *reinterpret_cast<unsigned*>(&m2), d);
        m2 = __hmax2(m2, *reinterpret_cast<__half2*>(&t));
        t = __shfl_xor_sync(0xffffffffu, *reinterpret_cast<unsigned*>(&m3), d);
        m3 = __hmax2(m3, *reinterpret_cast<__half2*>(&t));
    }

    // Mean = sum * 2^-5 (exact in fp16).
    const __half2 inv32 = __float2half2_rn(0.03125f);
    s0 = __hmul2(s0, inv32);
    s1 = __hmul2(s1, inv32);
    s2 = __hmul2(s2, inv32);
    s3 = __hmul2(s3, inv32);

    // One streaming STG.128 per lane:
    //  quad0: mean[8sub..+4)  quad1: mean[8sub+4..+8)
    //  quad2: max [8sub..+4)  quad3: max [8sub+4..+8)
    __half2 lo, hi;
    float* orow = out + (size_t)warp_id * 128;
    float* ptr;
    if (quad == 0)      { lo = s0; hi = s1; ptr = orow + 8 * sub; }
    else if (quad == 1) { lo = s2; hi = s3; ptr = orow + 8 * sub + 4; }
    else if (quad == 2) { lo = m0; hi = m1; ptr = orow + 64 + 8 * sub; }
    else                { lo = m2; hi = m3; ptr = orow + 64 + 8 * sub + 4; }

    const float2 fa = __half22float2(lo);
    const float2 fb = __half22float2(hi);
    stg_cs_f4(ptr, fa.x, fa.y, fb.x, fb.y);
}

extern "C" void kernel_launch(void* const* d_in, const int* in_sizes, int n_in,
                              void* d_out, int out_size) {
    const float* x = (const float*)d_in[0];   // [V, 64] f32
    const int* idxs = (const int*)d_in[1];    // [V, 32] i32
    float* out = (float*)d_out;               // [V, 128] f32

    const int V = in_sizes[1] / 32;

    const int n8 = V * (F_DIM / 8);
    convert_x_kernel<<<(n8 + 255) / 256, 256>>>(x, n8);

    const int threads = 256;  // 8 warps -> 8 vertices/block
    const int warps_per_block = threads / 32;
    const int blocks = (V + warps_per_block - 1) / warps_per_block;
    collect_nbr_avg_max_q<<<blocks, threads>>>(idxs, out, V);
}